// round 1
// baseline (speedup 1.0000x reference)
#include <cuda_runtime.h>
#include <cuda_bf16.h>
#include <cstddef>

#define BB 8
#define TT 2048
#define DD 1024
#define HH 128

// Scratch for Q/K/V projections (B*T=16384 rows x H=128) — 8 MB each.
__device__ float g_Q[BB * TT * HH];
__device__ float g_K[BB * TT * HH];
__device__ float g_V[BB * TT * HH];

// ---------------------------------------------------------------------------
// Kernel 1: fused QKV projection.  out[m][h] = in[m][:] . W[:,h] + b[h]
// M = 16384, K = 1024, N = 128.  blockIdx.y selects {K, Q, V}.
// 64(M) x 128(N) tile per block, 256 threads, 8x4 register tile per thread.
// ---------------------------------------------------------------------------
__global__ __launch_bounds__(256) void qkv_kernel(
    const float* __restrict__ att, const float* __restrict__ x,
    const float* __restrict__ Wk, const float* __restrict__ bk,
    const float* __restrict__ Wq, const float* __restrict__ bq,
    const float* __restrict__ Wv, const float* __restrict__ bv)
{
    const int which = blockIdx.y;
    const float* A    = (which == 2) ? x  : att;
    const float* W    = (which == 0) ? Wk : (which == 1) ? Wq : Wv;
    const float* bias = (which == 0) ? bk : (which == 1) ? bq : bv;
    float* Out        = (which == 0) ? g_K : (which == 1) ? g_Q : g_V;

    __shared__ float As[64][16];
    __shared__ float Ws[16][128];

    const int tid = threadIdx.x;
    const int tx  = tid % 32;   // N direction: cols tx*4 .. tx*4+3
    const int ty  = tid / 32;   // M direction: rows ty*8 .. ty*8+7
    const int m0  = blockIdx.x * 64;

    float acc[8][4];
#pragma unroll
    for (int i = 0; i < 8; i++)
#pragma unroll
        for (int j = 0; j < 4; j++) acc[i][j] = 0.f;

    const int lrow = tid / 4;   // A-load row within tile
    const int lc4  = tid % 4;   // A-load float4 column

    for (int kt = 0; kt < DD; kt += 16) {
        // Load A tile 64x16 (one float4 per thread)
        float4 av = *(const float4*)&A[(size_t)(m0 + lrow) * DD + kt + lc4 * 4];
        *(float4*)&As[lrow][lc4 * 4] = av;
        // Load W tile 16x128 (two float4 per thread)
#pragma unroll
        for (int r = 0; r < 2; r++) {
            int idx = tid + r * 256;       // float4 index in [0,512)
            int wr = idx / 32, wc = idx % 32;
            *(float4*)&Ws[wr][wc * 4] =
                *(const float4*)&W[(size_t)(kt + wr) * HH + wc * 4];
        }
        __syncthreads();
#pragma unroll
        for (int kk = 0; kk < 16; kk++) {
            float w0[4];
            *(float4*)w0 = *(float4*)&Ws[kk][tx * 4];
#pragma unroll
            for (int i = 0; i < 8; i++) {
                float a = As[ty * 8 + i][kk];
#pragma unroll
                for (int j = 0; j < 4; j++) acc[i][j] += a * w0[j];
            }
        }
        __syncthreads();
    }

    float b4[4];
    *(float4*)b4 = *(const float4*)&bias[tx * 4];
#pragma unroll
    for (int i = 0; i < 8; i++) {
        float4 o;
        o.x = acc[i][0] + b4[0];
        o.y = acc[i][1] + b4[1];
        o.z = acc[i][2] + b4[2];
        o.w = acc[i][3] + b4[3];
        *(float4*)&Out[(size_t)(m0 + ty * 8 + i) * HH + tx * 4] = o;
    }
}

// ---------------------------------------------------------------------------
// Kernel 2: flash attention, fp32.
// One block per (batch, 64-row q tile).  Streams 64-row K/V tiles with
// online softmax.  O accumulator in registers: 4 rows x 8 cols per thread.
// ---------------------------------------------------------------------------
struct AttnSmem {
    float Qs[64][132];   // padded: 132 % 32 == 4 -> 2-way worst case
    float Ks[64][132];
    float Vs[64][132];
    float Ss[64][68];    // scores / probabilities (68*4B = 16B aligned rows)
    float m_s[64];
    float l_s[64];
    float corr_s[64];
};

__global__ __launch_bounds__(256) void attn_kernel(float* __restrict__ out)
{
    extern __shared__ char smem_raw[];
    AttnSmem& sm = *reinterpret_cast<AttnSmem*>(smem_raw);

    const int b  = blockIdx.y;
    const int q0 = blockIdx.x * 64;
    const float scale = 11.313708498984761f;  // sqrt(128)

    const int tid = threadIdx.x;
    const int tx  = tid % 16;   // S cols tx*4..+3 ; O cols j*16+tx
    const int ty  = tid / 16;   // rows ty*4..+3

    // Load Q tile (64 x 128): 8 float4 per thread
    const float* Qg = g_Q + ((size_t)b * TT + q0) * HH;
#pragma unroll
    for (int r = 0; r < 8; r++) {
        int idx = tid + r * 256;
        int row = idx / 32, c4 = idx % 32;
        *(float4*)&sm.Qs[row][c4 * 4] = *(const float4*)&Qg[(size_t)row * HH + c4 * 4];
    }
    if (tid < 64) { sm.m_s[tid] = -1e30f; sm.l_s[tid] = 0.f; }

    float O[4][8];
#pragma unroll
    for (int i = 0; i < 4; i++)
#pragma unroll
        for (int j = 0; j < 8; j++) O[i][j] = 0.f;

    for (int k0 = 0; k0 < TT; k0 += 64) {
        const float* Kg = g_K + ((size_t)b * TT + k0) * HH;
        const float* Vg = g_V + ((size_t)b * TT + k0) * HH;

        __syncthreads();   // previous iteration's readers of Ks/Vs/Ss done
#pragma unroll
        for (int r = 0; r < 8; r++) {
            int idx = tid + r * 256;
            int row = idx / 32, c4 = idx % 32;
            *(float4*)&sm.Ks[row][c4 * 4] = *(const float4*)&Kg[(size_t)row * HH + c4 * 4];
            *(float4*)&sm.Vs[row][c4 * 4] = *(const float4*)&Vg[(size_t)row * HH + c4 * 4];
        }
        __syncthreads();

        // S[ty*4+i][tx*4+j] = scale * sum_d Q[row][d] * K[col][d]
        float s[4][4];
#pragma unroll
        for (int i = 0; i < 4; i++)
#pragma unroll
            for (int j = 0; j < 4; j++) s[i][j] = 0.f;

#pragma unroll 4
        for (int kk = 0; kk < 128; kk++) {
            float qv[4], kv[4];
#pragma unroll
            for (int i = 0; i < 4; i++) qv[i] = sm.Qs[ty * 4 + i][kk];
#pragma unroll
            for (int j = 0; j < 4; j++) kv[j] = sm.Ks[tx * 4 + j][kk];
#pragma unroll
            for (int i = 0; i < 4; i++)
#pragma unroll
                for (int j = 0; j < 4; j++) s[i][j] += qv[i] * kv[j];
        }
#pragma unroll
        for (int i = 0; i < 4; i++) {
            float4 sv;
            sv.x = s[i][0] * scale;
            sv.y = s[i][1] * scale;
            sv.z = s[i][2] * scale;
            sv.w = s[i][3] * scale;
            *(float4*)&sm.Ss[ty * 4 + i][tx * 4] = sv;
        }
        __syncthreads();

        // Online softmax: 4 threads per row, 16 cols each, shfl-reduce.
        {
            int row = tid >> 2, seg = (tid & 3) * 16;
            float mx = -1e30f;
#pragma unroll
            for (int c = 0; c < 16; c++) mx = fmaxf(mx, sm.Ss[row][seg + c]);
#pragma unroll
            for (int o = 1; o < 4; o <<= 1)
                mx = fmaxf(mx, __shfl_xor_sync(0xffffffffu, mx, o));
            float mold = sm.m_s[row];
            float mnew = fmaxf(mold, mx);
            float sum = 0.f;
#pragma unroll
            for (int c = 0; c < 16; c++) {
                float p = __expf(sm.Ss[row][seg + c] - mnew);
                sm.Ss[row][seg + c] = p;
                sum += p;
            }
#pragma unroll
            for (int o = 1; o < 4; o <<= 1)
                sum += __shfl_xor_sync(0xffffffffu, sum, o);
            if ((tid & 3) == 0) {
                float c = __expf(mold - mnew);
                sm.corr_s[row] = c;
                sm.l_s[row] = sm.l_s[row] * c + sum;
                sm.m_s[row] = mnew;
            }
        }
        __syncthreads();

        // O update: rescale then O += P @ V.  cols j*16+tx (stride-1 across lanes).
#pragma unroll
        for (int i = 0; i < 4; i++) {
            float c = sm.corr_s[ty * 4 + i];
#pragma unroll
            for (int j = 0; j < 8; j++) O[i][j] *= c;
        }
#pragma unroll 2
        for (int k = 0; k < 64; k++) {
            float p[4];
#pragma unroll
            for (int i = 0; i < 4; i++) p[i] = sm.Ss[ty * 4 + i][k];
            float vv[8];
#pragma unroll
            for (int j = 0; j < 8; j++) vv[j] = sm.Vs[k][j * 16 + tx];
#pragma unroll
            for (int i = 0; i < 4; i++)
#pragma unroll
                for (int j = 0; j < 8; j++) O[i][j] += p[i] * vv[j];
        }
    }

    // Normalize and store.
#pragma unroll
    for (int i = 0; i < 4; i++) {
        float inv = 1.f / sm.l_s[ty * 4 + i];
#pragma unroll
        for (int j = 0; j < 8; j++) {
            out[((size_t)b * TT + q0 + ty * 4 + i) * HH + j * 16 + tx] = O[i][j] * inv;
        }
    }
}

// ---------------------------------------------------------------------------
// Launch
// ---------------------------------------------------------------------------
extern "C" void kernel_launch(void* const* d_in, const int* in_sizes, int n_in,
                              void* d_out, int out_size)
{
    const float* x   = (const float*)d_in[0];
    const float* att = (const float*)d_in[1];
    const float* Wk  = (const float*)d_in[2];
    const float* bk  = (const float*)d_in[3];
    const float* Wq  = (const float*)d_in[4];
    const float* bq  = (const float*)d_in[5];
    const float* Wv  = (const float*)d_in[6];
    const float* bv  = (const float*)d_in[7];
    float* out = (float*)d_out;

    (void)in_sizes; (void)n_in; (void)out_size;

    qkv_kernel<<<dim3(TT * BB / 64, 3), 256>>>(att, x, Wk, bk, Wq, bq, Wv, bv);

    const int smem_bytes = (int)sizeof(AttnSmem);
    cudaFuncSetAttribute(attn_kernel,
                         cudaFuncAttributeMaxDynamicSharedMemorySize, smem_bytes);
    attn_kernel<<<dim3(TT / 64, BB), 256, smem_bytes>>>(out);
}

// round 2
// speedup vs baseline: 1.7495x; 1.7495x over previous
#include <cuda_runtime.h>
#include <cuda_bf16.h>
#include <cstddef>

#define BB 8
#define TT 2048
#define DD 1024
#define HH 128

__device__ float g_Q[BB * TT * HH];
__device__ float g_K[BB * TT * HH];
__device__ float g_V[BB * TT * HH];

__device__ __forceinline__ void cp_async16(void* smem_ptr, const void* gptr) {
    unsigned saddr = (unsigned)__cvta_generic_to_shared(smem_ptr);
    asm volatile("cp.async.cg.shared.global [%0], [%1], 16;\n" :: "r"(saddr), "l"(gptr));
}
#define CP_COMMIT()  asm volatile("cp.async.commit_group;\n" ::: "memory")
#define CP_WAIT1()   asm volatile("cp.async.wait_group 1;\n" ::: "memory")
#define CP_WAIT0()   asm volatile("cp.async.wait_group 0;\n" ::: "memory")

// ---------------------------------------------------------------------------
// Kernel 1: fused QKV projection. 128x128 tile, 256 threads, 8x8/thread,
// double-buffered smem (kt=16).
// ---------------------------------------------------------------------------
__global__ __launch_bounds__(256) void qkv_kernel(
    const float* __restrict__ att, const float* __restrict__ x,
    const float* __restrict__ Wk, const float* __restrict__ bk,
    const float* __restrict__ Wq, const float* __restrict__ bq,
    const float* __restrict__ Wv, const float* __restrict__ bv)
{
    const int which = blockIdx.y;
    const float* A    = (which == 2) ? x  : att;
    const float* W    = (which == 0) ? Wk : (which == 1) ? Wq : Wv;
    const float* bias = (which == 0) ? bk : (which == 1) ? bq : bv;
    float* Out        = (which == 0) ? g_K : (which == 1) ? g_Q : g_V;

    __shared__ float As[2][128][20];   // 20-float pad: 16B aligned, conflict-lite
    __shared__ float Ws[2][16][132];

    const int tid = threadIdx.x;
    const int tx  = tid % 16;          // output cols: tx*4+q + 64*g
    const int ty  = tid / 16;          // output rows: ty*8+i
    const int m0  = blockIdx.x * 128;

    float acc[8][8];
#pragma unroll
    for (int i = 0; i < 8; i++)
#pragma unroll
        for (int j = 0; j < 8; j++) acc[i][j] = 0.f;

    // A tile loader indices: 512 float4, 2/thread
    const int a_row0 = tid / 4,  a_c40 = tid % 4;           // r=0
    const int a_row1 = (tid + 256) / 4, a_c41 = (tid + 256) % 4;
    // W tile loader: 512 float4, 2/thread
    const int w_r0 = tid / 32, w_c0 = tid % 32;
    const int w_r1 = (tid + 256) / 32, w_c1 = (tid + 256) % 32;

    float4 a_ld0, a_ld1, w_ld0, w_ld1;

    // prologue: load kt=0
    a_ld0 = *(const float4*)&A[(size_t)(m0 + a_row0) * DD + a_c40 * 4];
    a_ld1 = *(const float4*)&A[(size_t)(m0 + a_row1) * DD + a_c41 * 4];
    w_ld0 = *(const float4*)&W[(size_t)w_r0 * HH + w_c0 * 4];
    w_ld1 = *(const float4*)&W[(size_t)w_r1 * HH + w_c1 * 4];
    *(float4*)&As[0][a_row0][a_c40 * 4] = a_ld0;
    *(float4*)&As[0][a_row1][a_c41 * 4] = a_ld1;
    *(float4*)&Ws[0][w_r0][w_c0 * 4] = w_ld0;
    *(float4*)&Ws[0][w_r1][w_c1 * 4] = w_ld1;
    __syncthreads();

    for (int it = 0; it < DD / 16; it++) {
        const int cur = it & 1;
        const int nxt = cur ^ 1;
        if (it < DD / 16 - 1) {
            const int kt = (it + 1) * 16;
            a_ld0 = *(const float4*)&A[(size_t)(m0 + a_row0) * DD + kt + a_c40 * 4];
            a_ld1 = *(const float4*)&A[(size_t)(m0 + a_row1) * DD + kt + a_c41 * 4];
            w_ld0 = *(const float4*)&W[(size_t)(kt + w_r0) * HH + w_c0 * 4];
            w_ld1 = *(const float4*)&W[(size_t)(kt + w_r1) * HH + w_c1 * 4];
        }
#pragma unroll
        for (int kk4 = 0; kk4 < 4; kk4++) {
            float4 a4[8];
#pragma unroll
            for (int i = 0; i < 8; i++)
                a4[i] = *(const float4*)&As[cur][ty * 8 + i][kk4 * 4];
#pragma unroll
            for (int kkin = 0; kkin < 4; kkin++) {
                const int kk = kk4 * 4 + kkin;
                float4 w0 = *(const float4*)&Ws[cur][kk][tx * 4];
                float4 w1 = *(const float4*)&Ws[cur][kk][64 + tx * 4];
                const float* w0f = (const float*)&w0;
                const float* w1f = (const float*)&w1;
#pragma unroll
                for (int i = 0; i < 8; i++) {
                    const float a = ((const float*)&a4[i])[kkin];
#pragma unroll
                    for (int q = 0; q < 4; q++) {
                        acc[i][q]     += a * w0f[q];
                        acc[i][4 + q] += a * w1f[q];
                    }
                }
            }
        }
        if (it < DD / 16 - 1) {
            *(float4*)&As[nxt][a_row0][a_c40 * 4] = a_ld0;
            *(float4*)&As[nxt][a_row1][a_c41 * 4] = a_ld1;
            *(float4*)&Ws[nxt][w_r0][w_c0 * 4] = w_ld0;
            *(float4*)&Ws[nxt][w_r1][w_c1 * 4] = w_ld1;
            __syncthreads();
        }
    }

    float4 b0 = *(const float4*)&bias[tx * 4];
    float4 b1 = *(const float4*)&bias[64 + tx * 4];
#pragma unroll
    for (int i = 0; i < 8; i++) {
        float4 o0, o1;
        o0.x = acc[i][0] + b0.x; o0.y = acc[i][1] + b0.y;
        o0.z = acc[i][2] + b0.z; o0.w = acc[i][3] + b0.w;
        o1.x = acc[i][4] + b1.x; o1.y = acc[i][5] + b1.y;
        o1.z = acc[i][6] + b1.z; o1.w = acc[i][7] + b1.w;
        *(float4*)&Out[(size_t)(m0 + ty * 8 + i) * HH + tx * 4]      = o0;
        *(float4*)&Out[(size_t)(m0 + ty * 8 + i) * HH + 64 + tx * 4] = o1;
    }
}

// ---------------------------------------------------------------------------
// Kernel 2: flash attention. 128-row q tile, 128-key tiles, 256 threads,
// 8x8 register tiles for both GEMMs, register-resident online softmax,
// P overwrites the K buffer, cp.async pipelining (V hidden behind S GEMM).
// ---------------------------------------------------------------------------
struct AttnSmem {
    float Q[128][132];
    float KP[128][132];   // K tile, later overwritten by P
    float V[128][132];
};

__global__ __launch_bounds__(256) void attn_kernel(float* __restrict__ out)
{
    extern __shared__ char smem_raw[];
    AttnSmem& sm = *reinterpret_cast<AttnSmem*>(smem_raw);

    const int b  = blockIdx.y;
    const int q0 = blockIdx.x * 128;
    const float scale = 11.313708498984761f;   // sqrt(128)

    const int tid = threadIdx.x;
    const int tx  = tid % 16;   // S cols: tx+16j ; O cols: tx*4+q+64g
    const int ty  = tid / 16;   // rows: ty*8+i

    // Load Q tile (128x128), pre-scaled by sqrt(H). 16 float4/thread.
    const float* Qg = g_Q + ((size_t)b * TT + q0) * HH;
#pragma unroll
    for (int r = 0; r < 16; r++) {
        const int idx = tid + r * 256;
        const int row = idx / 32, c4 = idx % 32;
        float4 v = *(const float4*)&Qg[(size_t)row * HH + c4 * 4];
        v.x *= scale; v.y *= scale; v.z *= scale; v.w *= scale;
        *(float4*)&sm.Q[row][c4 * 4] = v;
    }

    float O[8][8];
    float m_r[8], l_r[8];
#pragma unroll
    for (int i = 0; i < 8; i++) {
        m_r[i] = -1e30f; l_r[i] = 0.f;
#pragma unroll
        for (int j = 0; j < 8; j++) O[i][j] = 0.f;
    }
    __syncthreads();

    for (int k0 = 0; k0 < TT; k0 += 128) {
        const float* Kg = g_K + ((size_t)b * TT + k0) * HH;
        const float* Vg = g_V + ((size_t)b * TT + k0) * HH;

        // async loads: K group first, then V group
#pragma unroll
        for (int r = 0; r < 16; r++) {
            const int idx = tid + r * 256;
            const int row = idx / 32, c4 = idx % 32;
            cp_async16(&sm.KP[row][c4 * 4], &Kg[(size_t)row * HH + c4 * 4]);
        }
        CP_COMMIT();
#pragma unroll
        for (int r = 0; r < 16; r++) {
            const int idx = tid + r * 256;
            const int row = idx / 32, c4 = idx % 32;
            cp_async16(&sm.V[row][c4 * 4], &Vg[(size_t)row * HH + c4 * 4]);
        }
        CP_COMMIT();

        CP_WAIT1();         // K ready (V may still be in flight)
        __syncthreads();

        // S = Q K^T  (scaled already).  s[i][j]: row ty*8+i, col tx+16j.
        float s[8][8];
#pragma unroll
        for (int i = 0; i < 8; i++)
#pragma unroll
            for (int j = 0; j < 8; j++) s[i][j] = 0.f;

#pragma unroll 8
        for (int kk4 = 0; kk4 < 32; kk4++) {
            float4 q4[8];
#pragma unroll
            for (int i = 0; i < 8; i++)
                q4[i] = *(const float4*)&sm.Q[ty * 8 + i][kk4 * 4];
#pragma unroll
            for (int j = 0; j < 8; j++) {
                float4 k4 = *(const float4*)&sm.KP[tx + 16 * j][kk4 * 4];
#pragma unroll
                for (int i = 0; i < 8; i++) {
                    s[i][j] += q4[i].x * k4.x + q4[i].y * k4.y
                             + q4[i].z * k4.z + q4[i].w * k4.w;
                }
            }
        }
        __syncthreads();    // all warps done reading K -> reuse as P

        // online softmax in registers (16 tx lanes cooperate per row)
#pragma unroll
        for (int i = 0; i < 8; i++) {
            float mx = s[i][0];
#pragma unroll
            for (int j = 1; j < 8; j++) mx = fmaxf(mx, s[i][j]);
#pragma unroll
            for (int o = 1; o < 16; o <<= 1)
                mx = fmaxf(mx, __shfl_xor_sync(0xffffffffu, mx, o));
            const float mnew = fmaxf(m_r[i], mx);
            const float corr = __expf(m_r[i] - mnew);
            m_r[i] = mnew;
            float sum = 0.f;
#pragma unroll
            for (int j = 0; j < 8; j++) {
                const float p = __expf(s[i][j] - mnew);
                s[i][j] = p;
                sum += p;
            }
#pragma unroll
            for (int o = 1; o < 16; o <<= 1)
                sum += __shfl_xor_sync(0xffffffffu, sum, o);
            l_r[i] = l_r[i] * corr + sum;
#pragma unroll
            for (int j = 0; j < 8; j++) O[i][j] *= corr;
        }

        // store P into the K buffer
#pragma unroll
        for (int i = 0; i < 8; i++)
#pragma unroll
            for (int j = 0; j < 8; j++)
                sm.KP[ty * 8 + i][tx + 16 * j] = s[i][j];

        CP_WAIT0();          // V ready
        __syncthreads();     // P visible to all + V visible

        // O += P V.  O cols: tx*4+q (g=0), 64+tx*4+q (g=1).
#pragma unroll 4
        for (int k4 = 0; k4 < 32; k4++) {
            float4 p4[8];
#pragma unroll
            for (int i = 0; i < 8; i++)
                p4[i] = *(const float4*)&sm.KP[ty * 8 + i][k4 * 4];
#pragma unroll
            for (int kk = 0; kk < 4; kk++) {
                const int k = k4 * 4 + kk;
                float4 v0 = *(const float4*)&sm.V[k][tx * 4];
                float4 v1 = *(const float4*)&sm.V[k][64 + tx * 4];
                const float* v0f = (const float*)&v0;
                const float* v1f = (const float*)&v1;
#pragma unroll
                for (int i = 0; i < 8; i++) {
                    const float p = ((const float*)&p4[i])[kk];
#pragma unroll
                    for (int q = 0; q < 4; q++) {
                        O[i][q]     += p * v0f[q];
                        O[i][4 + q] += p * v1f[q];
                    }
                }
            }
        }
        __syncthreads();     // done reading P/V before next tile's cp.async
    }

    // normalize + store
#pragma unroll
    for (int i = 0; i < 8; i++) {
        const float inv = 1.f / l_r[i];
        float4 o0, o1;
        o0.x = O[i][0] * inv; o0.y = O[i][1] * inv;
        o0.z = O[i][2] * inv; o0.w = O[i][3] * inv;
        o1.x = O[i][4] * inv; o1.y = O[i][5] * inv;
        o1.z = O[i][6] * inv; o1.w = O[i][7] * inv;
        const size_t base = ((size_t)b * TT + q0 + ty * 8 + i) * HH;
        *(float4*)&out[base + tx * 4]      = o0;
        *(float4*)&out[base + 64 + tx * 4] = o1;
    }
}

// ---------------------------------------------------------------------------
// Launch
// ---------------------------------------------------------------------------
extern "C" void kernel_launch(void* const* d_in, const int* in_sizes, int n_in,
                              void* d_out, int out_size)
{
    const float* x   = (const float*)d_in[0];
    const float* att = (const float*)d_in[1];
    const float* Wk  = (const float*)d_in[2];
    const float* bk  = (const float*)d_in[3];
    const float* Wq  = (const float*)d_in[4];
    const float* bq  = (const float*)d_in[5];
    const float* Wv  = (const float*)d_in[6];
    const float* bv  = (const float*)d_in[7];
    float* out = (float*)d_out;

    (void)in_sizes; (void)n_in; (void)out_size;

    qkv_kernel<<<dim3(TT * BB / 128, 3), 256>>>(att, x, Wk, bk, Wq, bq, Wv, bv);

    const int smem_bytes = (int)sizeof(AttnSmem);
    cudaFuncSetAttribute(attn_kernel,
                         cudaFuncAttributeMaxDynamicSharedMemorySize, smem_bytes);
    attn_kernel<<<dim3(TT / 128, BB), 256, smem_bytes>>>(out);
}